// round 3
// baseline (speedup 1.0000x reference)
#include <cuda_runtime.h>
#include <cuda_bf16.h>

// Wrapped SAT box query.
// Reference decomposes separably: result[n,c] = sum_{a in Rset} sum_{b in Cset}
//   sgn_a*sgn_b * sat[ia, ib, c], where each axis contributes 2 (no wrap) or 3
//   (wrap) terms. Terms with index < 0 contribute 0 (reference's "bad" mask).
//
// i(u) = floor(u*512 - 0.5). u*512 is exact (power of two), -0.5 exact at these
// magnitudes -> indices match the JAX reference bitwise. All coordinate math
// uses single round-to-nearest ops (__fmul_rn/__fadd_rn/__fsub_rn) to mirror
// the reference's unfused op sequence.

#define HDIM 512
#define WDIM 512

__device__ __forceinline__ int sat_index(float u) {
    // floor(u * 512 - 0.5), exact
    return (int)floorf(__fsub_rn(__fmul_rn(u, 512.0f), 0.5f));
}

__global__ void sat_query_kernel(
    const float* __restrict__ sat,
    const float* __restrict__ x,
    const int*   __restrict__ p_start,
    float*       __restrict__ out,
    int C, int C_out)
{
    const int n = blockIdx.x;

    // ---- scalar setup (redundant per thread; cheap) ----
    const float4 q = __ldg(reinterpret_cast<const float4*>(x) + n);
    float cu = q.x, cv = q.y, du = q.z, dv = q.w;

    float hu = __fmul_rn(du, 0.5f);
    float hv = __fmul_rn(dv, 0.5f);
    float su = __fsub_rn(cu, hu), eu = __fadd_rn(cu, hu);
    float sv = __fsub_rn(cv, hv), ev = __fadd_rn(cv, hv);

    // nsuv = where(d<0, euv, suv); neuv = where(d<0, suv, euv)
    if (du < 0.0f) { float t = su; su = eu; eu = t; }
    if (dv < 0.0f) { float t = sv; sv = ev; ev = t; }

    // frac wrap (single sub, matches reference)
    su = __fsub_rn(su, floorf(su)); eu = __fsub_rn(eu, floorf(eu));
    sv = __fsub_rn(sv, floorf(sv)); ev = __fsub_rn(ev, floorf(ev));

    // ---- per-axis inclusion-exclusion lists (3 slots, dead slot => sign 0) ----
    // Rows (u axis, H):
    int   iu_e = sat_index(eu);        // in [-1, 511]
    int   iu_s = sat_index(su) - 1;    // in [-2, 510]  == i(su - 1/H)
    bool  wu   = (su > eu);            // wrap case
    int   rI0 = (iu_e >= 0) ? iu_e : 0;  float rS0 = (iu_e >= 0) ? 1.0f : 0.0f;
    int   rI1 = wu ? (HDIM - 1) : 0;     float rS1 = wu ? 1.0f : 0.0f;
    int   rI2 = (iu_s >= 0) ? iu_s : 0;  float rS2 = (iu_s >= 0) ? -1.0f : 0.0f;

    // Cols (v axis, W):
    int   iv_e = sat_index(ev);
    int   iv_s = sat_index(sv) - 1;
    bool  wv   = (sv > ev);
    int   cI0 = (iv_e >= 0) ? iv_e : 0;  float cS0 = (iv_e >= 0) ? 1.0f : 0.0f;
    int   cI1 = wv ? (WDIM - 1) : 0;     float cS1 = wv ? 1.0f : 0.0f;
    int   cI2 = (iv_s >= 0) ? iv_s : 0;  float cS2 = (iv_s >= 0) ? -1.0f : 0.0f;

    const int WC = WDIM * C;
    int r0 = rI0 * WC, r1 = rI1 * WC, r2 = rI2 * WC;
    int c0 = cI0 * C,  c1 = cI1 * C,  c2 = cI2 * C;

    // 9 combined offsets / signs (all compile-time-named registers)
    const int o00 = r0 + c0, o01 = r0 + c1, o02 = r0 + c2;
    const int o10 = r1 + c0, o11 = r1 + c1, o12 = r1 + c2;
    const int o20 = r2 + c0, o21 = r2 + c1, o22 = r2 + c2;
    const float w00 = rS0 * cS0, w01 = rS0 * cS1, w02 = rS0 * cS2;
    const float w10 = rS1 * cS0, w11 = rS1 * cS1, w12 = rS1 * cS2;
    const float w20 = rS2 * cS0, w21 = rS2 * cS1, w22 = rS2 * cS2;

    // channel slice offset (start_idx >= 0 selects a channel window)
    int s0 = *p_start;
    if (s0 < 0) s0 = 0;
    const float* __restrict__ satc = sat + s0;

    const size_t obase = (size_t)n * (size_t)C_out;

    // ---- channel loop: 9 independent loads -> full MLP, coalesced across tid ----
    for (int ch = threadIdx.x; ch < C_out; ch += blockDim.x) {
        float acc;
        acc = __fmul_rn(w00, satc[o00 + ch]);
        acc = fmaf(w01, satc[o01 + ch], acc);
        acc = fmaf(w02, satc[o02 + ch], acc);
        acc = fmaf(w10, satc[o10 + ch], acc);
        acc = fmaf(w11, satc[o11 + ch], acc);
        acc = fmaf(w12, satc[o12 + ch], acc);
        acc = fmaf(w20, satc[o20 + ch], acc);
        acc = fmaf(w21, satc[o21 + ch], acc);
        acc = fmaf(w22, satc[o22 + ch], acc);
        out[obase + ch] = acc;
    }
}

extern "C" void kernel_launch(void* const* d_in, const int* in_sizes, int n_in,
                              void* d_out, int out_size) {
    const float* sat   = (const float*)d_in[0];
    const float* x     = (const float*)d_in[1];
    const int*   start = (const int*)d_in[2];
    // d_in[3] (len_idx) is implied by out_size

    const int N     = in_sizes[1] / 4;
    const int C     = in_sizes[0] / (HDIM * WDIM);
    const int C_out = out_size / N;

    int bd = C_out;
    if (bd > 1024) bd = 1024;
    bd = ((bd + 31) / 32) * 32;
    if (bd < 32) bd = 32;

    sat_query_kernel<<<N, bd>>>(sat, x, start, (float*)d_out, C, C_out);
}

// round 4
// speedup vs baseline: 1.0009x; 1.0009x over previous
#include <cuda_runtime.h>
#include <cuda_bf16.h>

// Wrapped SAT box query.
// Reference decomposes separably: result[n,c] = sum_{a in Rset} sum_{b in Cset}
//   sgn_a*sgn_b * sat[ia, ib, c], where each axis contributes 2 (no wrap) or 3
//   (wrap) terms. Terms with index < 0 contribute 0 (reference's "bad" mask).
//
// i(u) = floor(u*512 - 0.5). u*512 is exact (power of two), -0.5 exact at these
// magnitudes -> indices match the JAX reference bitwise. All coordinate math
// uses single round-to-nearest ops (__fmul_rn/__fadd_rn/__fsub_rn) to mirror
// the reference's unfused op sequence.

#define HDIM 512
#define WDIM 512

__device__ __forceinline__ int sat_index(float u) {
    // floor(u * 512 - 0.5), exact
    return (int)floorf(__fsub_rn(__fmul_rn(u, 512.0f), 0.5f));
}

__global__ void sat_query_kernel(
    const float* __restrict__ sat,
    const float* __restrict__ x,
    const int*   __restrict__ p_start,
    float*       __restrict__ out,
    int C, int C_out)
{
    const int n = blockIdx.x;

    // ---- scalar setup (redundant per thread; cheap) ----
    const float4 q = __ldg(reinterpret_cast<const float4*>(x) + n);
    float cu = q.x, cv = q.y, du = q.z, dv = q.w;

    float hu = __fmul_rn(du, 0.5f);
    float hv = __fmul_rn(dv, 0.5f);
    float su = __fsub_rn(cu, hu), eu = __fadd_rn(cu, hu);
    float sv = __fsub_rn(cv, hv), ev = __fadd_rn(cv, hv);

    // nsuv = where(d<0, euv, suv); neuv = where(d<0, suv, euv)
    if (du < 0.0f) { float t = su; su = eu; eu = t; }
    if (dv < 0.0f) { float t = sv; sv = ev; ev = t; }

    // frac wrap (single sub, matches reference)
    su = __fsub_rn(su, floorf(su)); eu = __fsub_rn(eu, floorf(eu));
    sv = __fsub_rn(sv, floorf(sv)); ev = __fsub_rn(ev, floorf(ev));

    // ---- per-axis inclusion-exclusion lists (3 slots, dead slot => sign 0) ----
    // Rows (u axis, H):
    int   iu_e = sat_index(eu);        // in [-1, 511]
    int   iu_s = sat_index(su) - 1;    // in [-2, 510]  == i(su - 1/H)
    bool  wu   = (su > eu);            // wrap case
    int   rI0 = (iu_e >= 0) ? iu_e : 0;  float rS0 = (iu_e >= 0) ? 1.0f : 0.0f;
    int   rI1 = wu ? (HDIM - 1) : 0;     float rS1 = wu ? 1.0f : 0.0f;
    int   rI2 = (iu_s >= 0) ? iu_s : 0;  float rS2 = (iu_s >= 0) ? -1.0f : 0.0f;

    // Cols (v axis, W):
    int   iv_e = sat_index(ev);
    int   iv_s = sat_index(sv) - 1;
    bool  wv   = (sv > ev);
    int   cI0 = (iv_e >= 0) ? iv_e : 0;  float cS0 = (iv_e >= 0) ? 1.0f : 0.0f;
    int   cI1 = wv ? (WDIM - 1) : 0;     float cS1 = wv ? 1.0f : 0.0f;
    int   cI2 = (iv_s >= 0) ? iv_s : 0;  float cS2 = (iv_s >= 0) ? -1.0f : 0.0f;

    const int WC = WDIM * C;
    int r0 = rI0 * WC, r1 = rI1 * WC, r2 = rI2 * WC;
    int c0 = cI0 * C,  c1 = cI1 * C,  c2 = cI2 * C;

    // 9 combined offsets / signs (all compile-time-named registers)
    const int o00 = r0 + c0, o01 = r0 + c1, o02 = r0 + c2;
    const int o10 = r1 + c0, o11 = r1 + c1, o12 = r1 + c2;
    const int o20 = r2 + c0, o21 = r2 + c1, o22 = r2 + c2;
    const float w00 = rS0 * cS0, w01 = rS0 * cS1, w02 = rS0 * cS2;
    const float w10 = rS1 * cS0, w11 = rS1 * cS1, w12 = rS1 * cS2;
    const float w20 = rS2 * cS0, w21 = rS2 * cS1, w22 = rS2 * cS2;

    // channel slice offset (start_idx >= 0 selects a channel window)
    int s0 = *p_start;
    if (s0 < 0) s0 = 0;
    const float* __restrict__ satc = sat + s0;

    const size_t obase = (size_t)n * (size_t)C_out;

    // ---- channel loop: 9 independent loads -> full MLP, coalesced across tid ----
    for (int ch = threadIdx.x; ch < C_out; ch += blockDim.x) {
        float acc;
        acc = __fmul_rn(w00, satc[o00 + ch]);
        acc = fmaf(w01, satc[o01 + ch], acc);
        acc = fmaf(w02, satc[o02 + ch], acc);
        acc = fmaf(w10, satc[o10 + ch], acc);
        acc = fmaf(w11, satc[o11 + ch], acc);
        acc = fmaf(w12, satc[o12 + ch], acc);
        acc = fmaf(w20, satc[o20 + ch], acc);
        acc = fmaf(w21, satc[o21 + ch], acc);
        acc = fmaf(w22, satc[o22 + ch], acc);
        out[obase + ch] = acc;
    }
}

extern "C" void kernel_launch(void* const* d_in, const int* in_sizes, int n_in,
                              void* d_out, int out_size) {
    const float* sat   = (const float*)d_in[0];
    const float* x     = (const float*)d_in[1];
    const int*   start = (const int*)d_in[2];
    // d_in[3] (len_idx) is implied by out_size

    const int N     = in_sizes[1] / 4;
    const int C     = in_sizes[0] / (HDIM * WDIM);
    const int C_out = out_size / N;

    int bd = C_out;
    if (bd > 1024) bd = 1024;
    bd = ((bd + 31) / 32) * 32;
    if (bd < 32) bd = 32;

    sat_query_kernel<<<N, bd>>>(sat, x, start, (float*)d_out, C, C_out);
}